// round 10
// baseline (speedup 1.0000x reference)
#include <cuda_runtime.h>
#include <cstdint>

typedef unsigned long long ull;

// ---------------- scratch (device globals; 16B aligned, vector-load strides) ----------------
__device__ __align__(16) float g_x0[32 * 3 * 228 * 232];    // padded input, stride 232
__device__ __align__(16) float g_c1[32 * 32 * 116 * 120];   // conv1 out NCHW, stride 120
__device__ __align__(16) float g_c2[32 * 64 * 58 * 60];     // conv2 out NCHW, stride 60
__device__ __align__(16) float g_c3[32 * 56 * 56 * 128];    // conv3 out channels-LAST
__device__ __align__(16) float g_S [32 * 128 * 3200];       // samples, samp memory order [b][c][n]
__device__ __align__(16) float4 g_pw[32 * 32 * 100];
__device__ __align__(16) int4   g_po[32 * 32 * 100];
__device__ __align__(16) float g_w2p[64 * 32 * 25];
__device__ __align__(16) float g_w3p[128 * 64 * 9];

#define LEAK 0.2f

// ---------------- f32x2 helpers ----------------
__device__ __forceinline__ ull pack2(float lo, float hi) {
    ull r; asm("mov.b64 %0, {%1, %2};" : "=l"(r) : "f"(lo), "f"(hi)); return r;
}
__device__ __forceinline__ void unpack2(ull v, float& lo, float& hi) {
    asm("mov.b64 {%0, %1}, %2;" : "=f"(lo), "=f"(hi) : "l"(v));
}
__device__ __forceinline__ ull ffma2(ull a, ull b, ull c) {
    ull d; asm("fma.rn.f32x2 %0, %1, %2, %3;" : "=l"(d) : "l"(a), "l"(b), "l"(c)); return d;
}

// ---------------- merged pad + halo-zero ----------------
__global__ void padzero(const float* __restrict__ x)
{
    const int idx = blockIdx.x * blockDim.x + threadIdx.x;
    const int NA = 32 * 3 * 228 * 232;
    const int NB = 32 * 32 * 116 * 120;
    const int NC_ = 32 * 64 * 58 * 60;
    if (idx < NA) {
        const int wp = idx % 232;
        const int hp = (idx / 232) % 228;
        const int nc = idx / (232 * 228);
        const int h = hp - 2, w = wp - 2;
        float v = 0.0f;
        if (h >= 0 && h < 224 && w >= 0 && w < 224)
            v = x[(size_t)nc * 224 * 224 + h * 224 + w];
        g_x0[idx] = v;
    } else if (idx < NA + NB) {
        const int j = idx - NA;
        const int w = j % 120;
        const int h = (j / 120) % 116;
        if (h < 2 || h >= 114 || w < 2 || w >= 114) g_c1[j] = 0.0f;
    } else if (idx < NA + NB + NC_) {
        const int j = idx - NA - NB;
        const int w = j % 60;
        const int h = (j / 60) % 58;
        if (h < 1 || h >= 57 || w < 1 || w >= 57) g_c2[j] = 0.0f;
    }
}

// ---------------- weight permute: dst[g][(ci*KK+k)*QC + j] = wt[g*QC+j][ci][k] ----------------
__global__ void permute_wt(const float* __restrict__ wt, float* __restrict__ dst,
                           int CIN, int KK, int QC, int total)
{
    const int t = blockIdx.x * blockDim.x + threadIdx.x;
    if (t >= total) return;
    const int per = CIN * KK * QC;
    const int g = t / per;
    const int r = t % per;
    const int j   = r % QC;
    const int cik = r / QC;
    const int ci = cik / KK;
    const int k  = cik % KK;
    dst[t] = wt[((size_t)(g * QC + j) * CIN + ci) * KK + k];
}

// ---------------- conv + leaky, QC=8, software-pipelined input rows ----------------
template<int KS, int ST, int CIN, int QC, int PX, int OPAD, bool CLAST, bool GUARD, bool PERMW>
__global__ void __launch_bounds__(224, 3)
conv_pad(const float* __restrict__ in, const float* __restrict__ wsrc,
         const float* __restrict__ bias, float* __restrict__ out,
         int Wp, int chanStride, int Hout, int Wout, int Cout,
         int Wop, int outChanStride)
{
    constexpr int JP = QC / 2;
    constexpr int KK = KS * KS;
    constexpr int ISPAN = (PX - 1) * ST + KS;
    constexpr int NL4 = (ISPAN + 3) / 4;

    __shared__ __align__(16) float ws[CIN * KK * QC];

    const int coGroups = Cout / QC;
    const int bb    = blockIdx.z / coGroups;
    const int group = blockIdx.z % coGroups;
    const int cb    = group * QC;
    const int tid   = threadIdx.y * blockDim.x + threadIdx.x;
    const int nthr  = blockDim.x * blockDim.y;

    if (PERMW) {
        const float4* src = (const float4*)(wsrc + (size_t)group * CIN * KK * QC);
        float4* dst = (float4*)ws;
        const int n4 = CIN * KK * QC / 4;
        for (int i = tid; i < n4; i += nthr) dst[i] = src[i];
    } else {
        for (int idx = tid; idx < CIN * KK * QC; idx += nthr) {
            const int j   = idx % QC;
            const int cik = idx / QC;
            const int ci = cik / KK;
            const int k  = cik % KK;
            ws[idx] = wsrc[((size_t)(cb + j) * CIN + ci) * KK + k];
        }
    }
    __syncthreads();

    const int ox0 = threadIdx.x * PX;
    const int oy  = blockIdx.y * blockDim.y + threadIdx.y;
    if (GUARD && oy >= Hout) return;

    ull acc[JP][PX];
#pragma unroll
    for (int jp = 0; jp < JP; jp++) {
        const ull bv = pack2(bias[cb + 2 * jp], bias[cb + 2 * jp + 1]);
#pragma unroll
        for (int px = 0; px < PX; px++) acc[jp][px] = bv;
    }

    const float* ibase = in + (size_t)bb * CIN * chanStride + (size_t)(oy * ST) * Wp + ox0 * ST;

    // software pipeline: fn holds the NEXT input row's float4s
    float4 fn[NL4];
    {
        const float4* p0 = (const float4*)ibase;
#pragma unroll
        for (int l = 0; l < NL4; l++) fn[l] = p0[l];
    }

    for (int ci = 0; ci < CIN; ci++) {
        const float* crow = ibase + (size_t)ci * chanStride;
#pragma unroll
        for (int ky = 0; ky < KS; ky++) {
            // current row = fn (loaded one body ago)
            float4 f[NL4];
#pragma unroll
            for (int l = 0; l < NL4; l++) f[l] = fn[l];

            // issue prefetch of the next row NOW; consumer is a full body away
            {
                const float* nrow;
                if (ky < KS - 1) {
                    nrow = crow + (size_t)(ky + 1) * Wp;
                } else {
                    // next channel's row 0; for the very last body reload current (discarded)
                    nrow = (ci < CIN - 1) ? (crow + chanStride) : (crow + (size_t)ky * Wp);
                }
                const float4* np = (const float4*)nrow;
#pragma unroll
                for (int l = 0; l < NL4; l++) fn[l] = np[l];
            }

            ull bp[ISPAN];
#pragma unroll
            for (int t = 0; t < ISPAN; t++) {
                const int l = t >> 2, m = t & 3;
                const float v = (m == 0) ? f[l].x : (m == 1) ? f[l].y : (m == 2) ? f[l].z : f[l].w;
                bp[t] = pack2(v, v);
            }

            const float* wrow = ws + (ci * KK + ky * KS) * QC;
#pragma unroll
            for (int kx = 0; kx < KS; kx++) {
                ull w[JP];
#pragma unroll
                for (int jp = 0; jp < JP; jp++)
                    w[jp] = *(const ull*)(wrow + kx * QC + 2 * jp);
#pragma unroll
                for (int px = 0; px < PX; px++) {
                    const ull b2 = bp[px * ST + kx];
#pragma unroll
                    for (int jp = 0; jp < JP; jp++)
                        acc[jp][px] = ffma2(w[jp], b2, acc[jp][px]);
                }
            }
        }
    }

#pragma unroll
    for (int px = 0; px < PX; px++) {
        const int ox = ox0 + px;
        float v[QC];
#pragma unroll
        for (int jp = 0; jp < JP; jp++) {
            float lo, hi; unpack2(acc[jp][px], lo, hi);
            v[2 * jp]     = lo > 0.0f ? lo : LEAK * lo;
            v[2 * jp + 1] = hi > 0.0f ? hi : LEAK * hi;
        }
        if (CLAST) {
            float* dst = out + (((size_t)(bb * Hout + oy) * Wout + ox) * Cout) + cb;
#pragma unroll
            for (int q = 0; q < QC / 4; q++)
                *(float4*)(dst + q * 4) = make_float4(v[4 * q], v[4 * q + 1], v[4 * q + 2], v[4 * q + 3]);
        } else {
            const size_t base = (size_t)(oy + OPAD) * Wop + ox + OPAD;
#pragma unroll
            for (int j = 0; j < QC; j++)
                out[((size_t)bb * Cout + cb + j) * outChanStride + base] = v[j];
        }
    }
}

// ---------------- ROI coordinate / weight precompute ----------------
__global__ void roi_coords(const float* __restrict__ ROI)
{
    const int t = blockIdx.x * blockDim.x + threadIdx.x;
    if (t >= 32 * 32 * 100) return;
    const int b  = t / 3200;
    const int n  = t % 3200;
    const int rr = n / 100;
    const int g  = n % 100;
    const int gi = g / 10;
    const int gj = g % 10;

    const float* roi = ROI + ((size_t)(b * 32 + rr)) * 7;
    const float cx = roi[0], cy = roi[1];
    const float W1 = roi[2], W2 = roi[3];
    const float H1 = roi[4], H2 = roi[5];
    const float psi = roi[6];

    const float offx = ((float)gj - 4.5f) / 10.0f;
    const float offy = ((float)gi - 4.5f) / 10.0f;

    const float gx = offx * (W1 + W2) - (W1 - W2) * 0.5f;
    const float gy = offy * (H1 + H2) - (H1 - H2) * 0.5f;

    float s, c;
    sincosf(psi, &s, &c);
    const float x = gx * c + gy * s + cx;
    const float y = -gx * s + gy * c + cy;

    const int x0i = (int)floorf(x);
    const int y0i = (int)floorf(y);
    const int x0 = min(max(x0i, 0), 55);
    const int x1 = min(max(x0i + 1, 0), 55);
    const int y0 = min(max(y0i, 0), 55);
    const int y1 = min(max(y0i + 1, 0), 55);

    const float x0f = (float)x0, x1f = (float)x1;
    const float y0f = (float)y0, y1f = (float)y1;

    float step = (x1f - x0f) * (y1f - y0f);
    step = fminf(fmaxf(step, 0.001f), 2.0f);
    const float inv = 1.0f / step;

    float4 w;
    w.x = (x1f - x) * (y1f - y) * inv;
    w.y = (x1f - x) * (y - y0f) * inv;
    w.z = (x - x0f) * (y1f - y) * inv;
    w.w = (x - x0f) * (y - y0f) * inv;

    int4 o;
    o.x = (y0 * 56 + x0) * 128;
    o.y = (y1 * 56 + x0) * 128;
    o.z = (y0 * 56 + x1) * 128;
    o.w = (y1 * 56 + x1) * 128;

    g_pw[t] = w;
    g_po[t] = o;
}

// ---------------- bilinear sample + smem transpose ----------------
__global__ void roi_sample()
{
    __shared__ float sm[32][132];

    const int b  = blockIdx.y;
    const int n0 = blockIdx.x * 32;
    const int cq = threadIdx.x;
    const int y  = threadIdx.y;
    const int n  = n0 + y;

    const float4 w = g_pw[b * 3200 + n];
    const int4   o = g_po[b * 3200 + n];
    const float* feat = g_c3 + (size_t)b * 56 * 56 * 128;

    const float4 A = *(const float4*)(feat + o.x + cq * 4);
    const float4 B = *(const float4*)(feat + o.y + cq * 4);
    const float4 C = *(const float4*)(feat + o.z + cq * 4);
    const float4 D = *(const float4*)(feat + o.w + cq * 4);

    float4 r;
    r.x = A.x * w.x + B.x * w.y + C.x * w.z + D.x * w.w;
    r.y = A.y * w.x + B.y * w.y + C.y * w.z + D.y * w.w;
    r.z = A.z * w.x + B.z * w.y + C.z * w.z + D.z * w.w;
    r.w = A.w * w.x + B.w * w.y + C.w * w.z + D.w * w.w;

    *(float4*)&sm[y][cq * 4] = r;
    __syncthreads();

    const int tid = y * 32 + cq;
    const int c   = tid >> 3;
    const int nq  = tid & 7;
    float4 v;
    v.x = sm[nq * 4 + 0][c];
    v.y = sm[nq * 4 + 1][c];
    v.z = sm[nq * 4 + 2][c];
    v.w = sm[nq * 4 + 3][c];
    *(float4*)(g_S + ((size_t)(b * 128 + c)) * 3200 + n0 + nq * 4) = v;
}

// ---------------- FC ----------------
__global__ void fc_init(float* __restrict__ out, const float* __restrict__ fc_b)
{
    const int t = blockIdx.x * blockDim.x + threadIdx.x;
    if (t < 1024 * 256) out[t] = fc_b[t & 255];
}

// 64x64 tile, BK=32, 256 threads, 4x4/thread in f32x2, K split 8-way via atomicAdd.
__global__ void fc_gemm(const float* __restrict__ W, float* __restrict__ out)
{
    __shared__ __align__(16) float As2[32][132];
    __shared__ __align__(16) float Bs [32][68];

    const float* A = g_S;
    const int n0  = blockIdx.x * 64;
    const int m0  = blockIdx.y * 64;
    const int kb0 = blockIdx.z * 1600;

    const int tid = threadIdx.x;
    const int row = tid >> 2;
    const int kc  = (tid & 3) * 8;
    const int tr = tid >> 4;
    const int tc = tid & 15;

    ull acc2[4][2];
#pragma unroll
    for (int i = 0; i < 4; i++) { acc2[i][0] = 0ull; acc2[i][1] = 0ull; }

    for (int kb = kb0; kb < kb0 + 1600; kb += 32) {
        const float4 a0 = *(const float4*)(A + (size_t)(m0 + row) * 12800 + kb + kc);
        const float4 a1 = *(const float4*)(A + (size_t)(m0 + row) * 12800 + kb + kc + 4);
        const float4 b0 = *(const float4*)(W + (size_t)(n0 + row) * 12800 + kb + kc);
        const float4 b1 = *(const float4*)(W + (size_t)(n0 + row) * 12800 + kb + kc + 4);

        *(ull*)&As2[kc + 0][row * 2] = pack2(a0.x, a0.x);
        *(ull*)&As2[kc + 1][row * 2] = pack2(a0.y, a0.y);
        *(ull*)&As2[kc + 2][row * 2] = pack2(a0.z, a0.z);
        *(ull*)&As2[kc + 3][row * 2] = pack2(a0.w, a0.w);
        *(ull*)&As2[kc + 4][row * 2] = pack2(a1.x, a1.x);
        *(ull*)&As2[kc + 5][row * 2] = pack2(a1.y, a1.y);
        *(ull*)&As2[kc + 6][row * 2] = pack2(a1.z, a1.z);
        *(ull*)&As2[kc + 7][row * 2] = pack2(a1.w, a1.w);
        Bs[kc + 0][row] = b0.x;  Bs[kc + 1][row] = b0.y;
        Bs[kc + 2][row] = b0.z;  Bs[kc + 3][row] = b0.w;
        Bs[kc + 4][row] = b1.x;  Bs[kc + 5][row] = b1.y;
        Bs[kc + 6][row] = b1.z;  Bs[kc + 7][row] = b1.w;
        __syncthreads();

#pragma unroll
        for (int kk = 0; kk < 32; kk++) {
            const ulonglong2 a01 = *(const ulonglong2*)&As2[kk][tr * 8];
            const ulonglong2 a23 = *(const ulonglong2*)&As2[kk][tr * 8 + 4];
            const ulonglong2 b01 = *(const ulonglong2*)&Bs[kk][tc * 4];
            acc2[0][0] = ffma2(a01.x, b01.x, acc2[0][0]);
            acc2[0][1] = ffma2(a01.x, b01.y, acc2[0][1]);
            acc2[1][0] = ffma2(a01.y, b01.x, acc2[1][0]);
            acc2[1][1] = ffma2(a01.y, b01.y, acc2[1][1]);
            acc2[2][0] = ffma2(a23.x, b01.x, acc2[2][0]);
            acc2[2][1] = ffma2(a23.x, b01.y, acc2[2][1]);
            acc2[3][0] = ffma2(a23.y, b01.x, acc2[3][0]);
            acc2[3][1] = ffma2(a23.y, b01.y, acc2[3][1]);
        }
        __syncthreads();
    }

#pragma unroll
    for (int i = 0; i < 4; i++)
#pragma unroll
        for (int h = 0; h < 2; h++) {
            float f0, f1; unpack2(acc2[i][h], f0, f1);
            float* dst = out + (size_t)(m0 + tr * 4 + i) * 256 + n0 + tc * 4 + h * 2;
            atomicAdd(dst + 0, f0);
            atomicAdd(dst + 1, f1);
        }
}

// ---------------- launch ----------------
extern "C" void kernel_launch(void* const* d_in, const int* in_sizes, int n_in,
                              void* d_out, int out_size)
{
    const float* x    = (const float*)d_in[0];
    const float* ROI  = (const float*)d_in[1];
    const float* w1   = (const float*)d_in[2];
    const float* b1   = (const float*)d_in[3];
    const float* w2   = (const float*)d_in[4];
    const float* b2   = (const float*)d_in[5];
    const float* w3   = (const float*)d_in[6];
    const float* b3   = (const float*)d_in[7];
    const float* fc_w = (const float*)d_in[8];
    const float* fc_b = (const float*)d_in[9];
    float* out = (float*)d_out;

    float *p_x0, *p_c1, *p_c2, *p_c3, *p_w2p, *p_w3p;
    cudaGetSymbolAddress((void**)&p_x0, g_x0);
    cudaGetSymbolAddress((void**)&p_c1, g_c1);
    cudaGetSymbolAddress((void**)&p_c2, g_c2);
    cudaGetSymbolAddress((void**)&p_c3, g_c3);
    cudaGetSymbolAddress((void**)&p_w2p, g_w2p);
    cudaGetSymbolAddress((void**)&p_w3p, g_w3p);

    const int NPZ = 32 * 3 * 228 * 232 + 32 * 32 * 116 * 120 + 32 * 64 * 58 * 60;

    // 0: pad input + zero halos (merged)
    padzero<<<(NPZ + 255) / 256, 256>>>(x);
    // 1: permute conv2 weights (QC=8 grouping)
    permute_wt<<<(64 * 32 * 25 + 255) / 256, 256>>>(w2, p_w2p, 32, 25, 8, 64 * 32 * 25);
    // 2: conv1 (inline weight staging): 3 -> 32, 5x5 s2, 224 -> 112
    conv_pad<5, 2, 3, 8, 4, 2, false, false, false><<<dim3(1, 14, 32 * 4), dim3(28, 8)>>>(
        p_x0, w1, b1, p_c1, 232, 228 * 232, 112, 112, 32, 120, 116 * 120);
    // 3: conv2 (PROFILED SLOT): 32 -> 64, 5x5 s2, 112 -> 56
    conv_pad<5, 2, 32, 8, 4, 1, false, true, true><<<dim3(1, 4, 32 * 8), dim3(14, 16)>>>(
        p_c1, p_w2p, b2, p_c2, 120, 116 * 120, 56, 56, 64, 60, 58 * 60);
    // 4: permute conv3 weights (QC=8 grouping)
    permute_wt<<<(128 * 64 * 9 + 255) / 256, 256>>>(w3, p_w3p, 64, 9, 8, 128 * 64 * 9);
    // 5: conv3: 64 -> 128, 3x3 s1, 56 -> 56, channels-last out
    conv_pad<3, 1, 64, 8, 4, 0, true, true, true><<<dim3(1, 4, 32 * 16), dim3(14, 16)>>>(
        p_c2, p_w3p, b3, p_c3, 60, 58 * 60, 56, 56, 128, 0, 0);
    // 6: ROI coords
    roi_coords<<<(32 * 32 * 100 + 255) / 256, 256>>>(ROI);
    // 7: sampling
    roi_sample<<<dim3(100, 32), dim3(32, 32)>>>();
    // 8-9: FC
    fc_init<<<1024, 256>>>(out, fc_b);
    fc_gemm<<<dim3(4, 16, 8), 256>>>(fc_w, out);
}

// round 11
// speedup vs baseline: 1.0559x; 1.0559x over previous
#include <cuda_runtime.h>
#include <cstdint>

typedef unsigned long long ull;

// ---------------- scratch (device globals; 16B aligned, vector-load strides) ----------------
__device__ __align__(16) float g_x0[32 * 3 * 228 * 232];    // padded input, stride 232
__device__ __align__(16) float g_c1[32 * 32 * 116 * 120];   // conv1 out NCHW, stride 120
__device__ __align__(16) float g_c2[32 * 64 * 58 * 60];     // conv2 out NCHW, stride 60
__device__ __align__(16) float g_c3[32 * 56 * 56 * 128];    // conv3 out channels-LAST
__device__ __align__(16) float g_S [32 * 128 * 3200];       // samples, samp memory order [b][c][n]
__device__ __align__(16) float4 g_pw[32 * 32 * 100];
__device__ __align__(16) int4   g_po[32 * 32 * 100];
__device__ __align__(16) float g_w2p[64 * 32 * 25];
__device__ __align__(16) float g_w3p[128 * 64 * 9];

#define LEAK 0.2f

// ---------------- f32x2 helpers ----------------
__device__ __forceinline__ ull pack2(float lo, float hi) {
    ull r; asm("mov.b64 %0, {%1, %2};" : "=l"(r) : "f"(lo), "f"(hi)); return r;
}
__device__ __forceinline__ void unpack2(ull v, float& lo, float& hi) {
    asm("mov.b64 {%0, %1}, %2;" : "=f"(lo), "=f"(hi) : "l"(v));
}
__device__ __forceinline__ ull ffma2(ull a, ull b, ull c) {
    ull d; asm("fma.rn.f32x2 %0, %1, %2, %3;" : "=l"(d) : "l"(a), "l"(b), "l"(c)); return d;
}

// ---------------- merged pad + halo-zero ----------------
__global__ void padzero(const float* __restrict__ x)
{
    const int idx = blockIdx.x * blockDim.x + threadIdx.x;
    const int NA = 32 * 3 * 228 * 232;
    const int NB = 32 * 32 * 116 * 120;
    const int NC_ = 32 * 64 * 58 * 60;
    if (idx < NA) {
        const int wp = idx % 232;
        const int hp = (idx / 232) % 228;
        const int nc = idx / (232 * 228);
        const int h = hp - 2, w = wp - 2;
        float v = 0.0f;
        if (h >= 0 && h < 224 && w >= 0 && w < 224)
            v = x[(size_t)nc * 224 * 224 + h * 224 + w];
        g_x0[idx] = v;
    } else if (idx < NA + NB) {
        const int j = idx - NA;
        const int w = j % 120;
        const int h = (j / 120) % 116;
        if (h < 2 || h >= 114 || w < 2 || w >= 114) g_c1[j] = 0.0f;
    } else if (idx < NA + NB + NC_) {
        const int j = idx - NA - NB;
        const int w = j % 60;
        const int h = (j / 60) % 58;
        if (h < 1 || h >= 57 || w < 1 || w >= 57) g_c2[j] = 0.0f;
    }
}

// ---------------- weight permute: dst[g][(ci*KK+k)*QC + j] = wt[g*QC+j][ci][k] ----------------
__global__ void permute_wt(const float* __restrict__ wt, float* __restrict__ dst,
                           int CIN, int KK, int QC, int total)
{
    const int t = blockIdx.x * blockDim.x + threadIdx.x;
    if (t >= total) return;
    const int per = CIN * KK * QC;
    const int g = t / per;
    const int r = t % per;
    const int j   = r % QC;
    const int cik = r / QC;
    const int ci = cik / KK;
    const int k  = cik % KK;
    dst[t] = wt[((size_t)(g * QC + j) * CIN + ci) * KK + k];
}

// ---------------- conv + leaky, QC=8, direct LDG.128 input, LDS.128 weight pairs ----------------
template<int KS, int ST, int CIN, int QC, int PX, int OPAD, bool CLAST, bool GUARD, bool PERMW>
__global__ void __launch_bounds__(224, 4)
conv_pad(const float* __restrict__ in, const float* __restrict__ wsrc,
         const float* __restrict__ bias, float* __restrict__ out,
         int Wp, int chanStride, int Hout, int Wout, int Cout,
         int Wop, int outChanStride)
{
    constexpr int JP = QC / 2;
    constexpr int KK = KS * KS;
    constexpr int ISPAN = (PX - 1) * ST + KS;
    constexpr int NL4 = (ISPAN + 3) / 4;

    __shared__ __align__(16) float ws[CIN * KK * QC];

    const int coGroups = Cout / QC;
    const int bb    = blockIdx.z / coGroups;
    const int group = blockIdx.z % coGroups;
    const int cb    = group * QC;
    const int tid   = threadIdx.y * blockDim.x + threadIdx.x;
    const int nthr  = blockDim.x * blockDim.y;

    if (PERMW) {
        const float4* src = (const float4*)(wsrc + (size_t)group * CIN * KK * QC);
        float4* dst = (float4*)ws;
        const int n4 = CIN * KK * QC / 4;
        for (int i = tid; i < n4; i += nthr) dst[i] = src[i];
    } else {
        for (int idx = tid; idx < CIN * KK * QC; idx += nthr) {
            const int j   = idx % QC;
            const int cik = idx / QC;
            const int ci = cik / KK;
            const int k  = cik % KK;
            ws[idx] = wsrc[((size_t)(cb + j) * CIN + ci) * KK + k];
        }
    }
    __syncthreads();

    const int ox0 = threadIdx.x * PX;
    const int oy  = blockIdx.y * blockDim.y + threadIdx.y;
    if (GUARD && oy >= Hout) return;

    ull acc[JP][PX];
#pragma unroll
    for (int jp = 0; jp < JP; jp++) {
        const ull bv = pack2(bias[cb + 2 * jp], bias[cb + 2 * jp + 1]);
#pragma unroll
        for (int px = 0; px < PX; px++) acc[jp][px] = bv;
    }

    const float* ibase = in + (size_t)bb * CIN * chanStride + (size_t)(oy * ST) * Wp + ox0 * ST;

    for (int ci = 0; ci < CIN; ci++) {
        const float* ip = ibase + (size_t)ci * chanStride;
#pragma unroll
        for (int ky = 0; ky < KS; ky++) {
            const float4* rowq = (const float4*)(ip + (size_t)ky * Wp);

            float4 f[NL4];
#pragma unroll
            for (int l = 0; l < NL4; l++) f[l] = rowq[l];

            ull bp[ISPAN];
#pragma unroll
            for (int t = 0; t < ISPAN; t++) {
                const int l = t >> 2, m = t & 3;
                const float v = (m == 0) ? f[l].x : (m == 1) ? f[l].y : (m == 2) ? f[l].z : f[l].w;
                bp[t] = pack2(v, v);
            }

            const float* wrow = ws + (ci * KK + ky * KS) * QC;
#pragma unroll
            for (int kx = 0; kx < KS; kx++) {
                // LDS.128 weight pairs: (w0,w1) and (w2,w3) — wrow + kx*QC is 16B aligned
                const ulonglong2* wq = (const ulonglong2*)(wrow + kx * QC);
                const ulonglong2 wa = wq[0];
                const ulonglong2 wb = wq[1];
#pragma unroll
                for (int px = 0; px < PX; px++) {
                    const ull b2 = bp[px * ST + kx];
                    acc[0][px] = ffma2(wa.x, b2, acc[0][px]);
                    acc[1][px] = ffma2(wa.y, b2, acc[1][px]);
                    acc[2][px] = ffma2(wb.x, b2, acc[2][px]);
                    acc[3][px] = ffma2(wb.y, b2, acc[3][px]);
                }
            }
        }
    }

#pragma unroll
    for (int px = 0; px < PX; px++) {
        const int ox = ox0 + px;
        float v[QC];
#pragma unroll
        for (int jp = 0; jp < JP; jp++) {
            float lo, hi; unpack2(acc[jp][px], lo, hi);
            v[2 * jp]     = lo > 0.0f ? lo : LEAK * lo;
            v[2 * jp + 1] = hi > 0.0f ? hi : LEAK * hi;
        }
        if (CLAST) {
            float* dst = out + (((size_t)(bb * Hout + oy) * Wout + ox) * Cout) + cb;
#pragma unroll
            for (int q = 0; q < QC / 4; q++)
                *(float4*)(dst + q * 4) = make_float4(v[4 * q], v[4 * q + 1], v[4 * q + 2], v[4 * q + 3]);
        } else {
            const size_t base = (size_t)(oy + OPAD) * Wop + ox + OPAD;
#pragma unroll
            for (int j = 0; j < QC; j++)
                out[((size_t)bb * Cout + cb + j) * outChanStride + base] = v[j];
        }
    }
}

// ---------------- ROI coordinate / weight precompute ----------------
__global__ void roi_coords(const float* __restrict__ ROI)
{
    const int t = blockIdx.x * blockDim.x + threadIdx.x;
    if (t >= 32 * 32 * 100) return;
    const int b  = t / 3200;
    const int n  = t % 3200;
    const int rr = n / 100;
    const int g  = n % 100;
    const int gi = g / 10;
    const int gj = g % 10;

    const float* roi = ROI + ((size_t)(b * 32 + rr)) * 7;
    const float cx = roi[0], cy = roi[1];
    const float W1 = roi[2], W2 = roi[3];
    const float H1 = roi[4], H2 = roi[5];
    const float psi = roi[6];

    const float offx = ((float)gj - 4.5f) / 10.0f;
    const float offy = ((float)gi - 4.5f) / 10.0f;

    const float gx = offx * (W1 + W2) - (W1 - W2) * 0.5f;
    const float gy = offy * (H1 + H2) - (H1 - H2) * 0.5f;

    float s, c;
    sincosf(psi, &s, &c);
    const float x = gx * c + gy * s + cx;
    const float y = -gx * s + gy * c + cy;

    const int x0i = (int)floorf(x);
    const int y0i = (int)floorf(y);
    const int x0 = min(max(x0i, 0), 55);
    const int x1 = min(max(x0i + 1, 0), 55);
    const int y0 = min(max(y0i, 0), 55);
    const int y1 = min(max(y0i + 1, 0), 55);

    const float x0f = (float)x0, x1f = (float)x1;
    const float y0f = (float)y0, y1f = (float)y1;

    float step = (x1f - x0f) * (y1f - y0f);
    step = fminf(fmaxf(step, 0.001f), 2.0f);
    const float inv = 1.0f / step;

    float4 w;
    w.x = (x1f - x) * (y1f - y) * inv;
    w.y = (x1f - x) * (y - y0f) * inv;
    w.z = (x - x0f) * (y1f - y) * inv;
    w.w = (x - x0f) * (y - y0f) * inv;

    int4 o;
    o.x = (y0 * 56 + x0) * 128;
    o.y = (y1 * 56 + x0) * 128;
    o.z = (y0 * 56 + x1) * 128;
    o.w = (y1 * 56 + x1) * 128;

    g_pw[t] = w;
    g_po[t] = o;
}

// ---------------- bilinear sample + smem transpose ----------------
__global__ void roi_sample()
{
    __shared__ float sm[32][132];

    const int b  = blockIdx.y;
    const int n0 = blockIdx.x * 32;
    const int cq = threadIdx.x;
    const int y  = threadIdx.y;
    const int n  = n0 + y;

    const float4 w = g_pw[b * 3200 + n];
    const int4   o = g_po[b * 3200 + n];
    const float* feat = g_c3 + (size_t)b * 56 * 56 * 128;

    const float4 A = *(const float4*)(feat + o.x + cq * 4);
    const float4 B = *(const float4*)(feat + o.y + cq * 4);
    const float4 C = *(const float4*)(feat + o.z + cq * 4);
    const float4 D = *(const float4*)(feat + o.w + cq * 4);

    float4 r;
    r.x = A.x * w.x + B.x * w.y + C.x * w.z + D.x * w.w;
    r.y = A.y * w.x + B.y * w.y + C.y * w.z + D.y * w.w;
    r.z = A.z * w.x + B.z * w.y + C.z * w.z + D.z * w.w;
    r.w = A.w * w.x + B.w * w.y + C.w * w.z + D.w * w.w;

    *(float4*)&sm[y][cq * 4] = r;
    __syncthreads();

    const int tid = y * 32 + cq;
    const int c   = tid >> 3;
    const int nq  = tid & 7;
    float4 v;
    v.x = sm[nq * 4 + 0][c];
    v.y = sm[nq * 4 + 1][c];
    v.z = sm[nq * 4 + 2][c];
    v.w = sm[nq * 4 + 3][c];
    *(float4*)(g_S + ((size_t)(b * 128 + c)) * 3200 + n0 + nq * 4) = v;
}

// ---------------- FC ----------------
__global__ void fc_init(float* __restrict__ out, const float* __restrict__ fc_b)
{
    const int t = blockIdx.x * blockDim.x + threadIdx.x;
    if (t < 1024 * 256) out[t] = fc_b[t & 255];
}

// 64x64 tile, BK=32, 256 threads, 4x4/thread in f32x2, K split 8-way via atomicAdd.
__global__ void fc_gemm(const float* __restrict__ W, float* __restrict__ out)
{
    __shared__ __align__(16) float As2[32][132];
    __shared__ __align__(16) float Bs [32][68];

    const float* A = g_S;
    const int n0  = blockIdx.x * 64;
    const int m0  = blockIdx.y * 64;
    const int kb0 = blockIdx.z * 1600;

    const int tid = threadIdx.x;
    const int row = tid >> 2;
    const int kc  = (tid & 3) * 8;
    const int tr = tid >> 4;
    const int tc = tid & 15;

    ull acc2[4][2];
#pragma unroll
    for (int i = 0; i < 4; i++) { acc2[i][0] = 0ull; acc2[i][1] = 0ull; }

    for (int kb = kb0; kb < kb0 + 1600; kb += 32) {
        const float4 a0 = *(const float4*)(A + (size_t)(m0 + row) * 12800 + kb + kc);
        const float4 a1 = *(const float4*)(A + (size_t)(m0 + row) * 12800 + kb + kc + 4);
        const float4 b0 = *(const float4*)(W + (size_t)(n0 + row) * 12800 + kb + kc);
        const float4 b1 = *(const float4*)(W + (size_t)(n0 + row) * 12800 + kb + kc + 4);

        *(ull*)&As2[kc + 0][row * 2] = pack2(a0.x, a0.x);
        *(ull*)&As2[kc + 1][row * 2] = pack2(a0.y, a0.y);
        *(ull*)&As2[kc + 2][row * 2] = pack2(a0.z, a0.z);
        *(ull*)&As2[kc + 3][row * 2] = pack2(a0.w, a0.w);
        *(ull*)&As2[kc + 4][row * 2] = pack2(a1.x, a1.x);
        *(ull*)&As2[kc + 5][row * 2] = pack2(a1.y, a1.y);
        *(ull*)&As2[kc + 6][row * 2] = pack2(a1.z, a1.z);
        *(ull*)&As2[kc + 7][row * 2] = pack2(a1.w, a1.w);
        Bs[kc + 0][row] = b0.x;  Bs[kc + 1][row] = b0.y;
        Bs[kc + 2][row] = b0.z;  Bs[kc + 3][row] = b0.w;
        Bs[kc + 4][row] = b1.x;  Bs[kc + 5][row] = b1.y;
        Bs[kc + 6][row] = b1.z;  Bs[kc + 7][row] = b1.w;
        __syncthreads();

#pragma unroll
        for (int kk = 0; kk < 32; kk++) {
            const ulonglong2 a01 = *(const ulonglong2*)&As2[kk][tr * 8];
            const ulonglong2 a23 = *(const ulonglong2*)&As2[kk][tr * 8 + 4];
            const ulonglong2 b01 = *(const ulonglong2*)&Bs[kk][tc * 4];
            acc2[0][0] = ffma2(a01.x, b01.x, acc2[0][0]);
            acc2[0][1] = ffma2(a01.x, b01.y, acc2[0][1]);
            acc2[1][0] = ffma2(a01.y, b01.x, acc2[1][0]);
            acc2[1][1] = ffma2(a01.y, b01.y, acc2[1][1]);
            acc2[2][0] = ffma2(a23.x, b01.x, acc2[2][0]);
            acc2[2][1] = ffma2(a23.x, b01.y, acc2[2][1]);
            acc2[3][0] = ffma2(a23.y, b01.x, acc2[3][0]);
            acc2[3][1] = ffma2(a23.y, b01.y, acc2[3][1]);
        }
        __syncthreads();
    }

#pragma unroll
    for (int i = 0; i < 4; i++)
#pragma unroll
        for (int h = 0; h < 2; h++) {
            float f0, f1; unpack2(acc2[i][h], f0, f1);
            float* dst = out + (size_t)(m0 + tr * 4 + i) * 256 + n0 + tc * 4 + h * 2;
            atomicAdd(dst + 0, f0);
            atomicAdd(dst + 1, f1);
        }
}

// ---------------- launch ----------------
extern "C" void kernel_launch(void* const* d_in, const int* in_sizes, int n_in,
                              void* d_out, int out_size)
{
    const float* x    = (const float*)d_in[0];
    const float* ROI  = (const float*)d_in[1];
    const float* w1   = (const float*)d_in[2];
    const float* b1   = (const float*)d_in[3];
    const float* w2   = (const float*)d_in[4];
    const float* b2   = (const float*)d_in[5];
    const float* w3   = (const float*)d_in[6];
    const float* b3   = (const float*)d_in[7];
    const float* fc_w = (const float*)d_in[8];
    const float* fc_b = (const float*)d_in[9];
    float* out = (float*)d_out;

    float *p_x0, *p_c1, *p_c2, *p_c3, *p_w2p, *p_w3p;
    cudaGetSymbolAddress((void**)&p_x0, g_x0);
    cudaGetSymbolAddress((void**)&p_c1, g_c1);
    cudaGetSymbolAddress((void**)&p_c2, g_c2);
    cudaGetSymbolAddress((void**)&p_c3, g_c3);
    cudaGetSymbolAddress((void**)&p_w2p, g_w2p);
    cudaGetSymbolAddress((void**)&p_w3p, g_w3p);

    const int NPZ = 32 * 3 * 228 * 232 + 32 * 32 * 116 * 120 + 32 * 64 * 58 * 60;

    // 0: pad input + zero halos (merged)
    padzero<<<(NPZ + 255) / 256, 256>>>(x);
    // 1: permute conv2 weights (QC=8 grouping)
    permute_wt<<<(64 * 32 * 25 + 255) / 256, 256>>>(w2, p_w2p, 32, 25, 8, 64 * 32 * 25);
    // 2: conv1 (inline weight staging): 3 -> 32, 5x5 s2, 224 -> 112
    conv_pad<5, 2, 3, 8, 4, 2, false, false, false><<<dim3(1, 14, 32 * 4), dim3(28, 8)>>>(
        p_x0, w1, b1, p_c1, 232, 228 * 232, 112, 112, 32, 120, 116 * 120);
    // 3: conv2 (PROFILED SLOT): 32 -> 64, 5x5 s2, 112 -> 56
    conv_pad<5, 2, 32, 8, 4, 1, false, true, true><<<dim3(1, 4, 32 * 8), dim3(14, 16)>>>(
        p_c1, p_w2p, b2, p_c2, 120, 116 * 120, 56, 56, 64, 60, 58 * 60);
    // 4: permute conv3 weights (QC=8 grouping)
    permute_wt<<<(128 * 64 * 9 + 255) / 256, 256>>>(w3, p_w3p, 64, 9, 8, 128 * 64 * 9);
    // 5: conv3: 64 -> 128, 3x3 s1, 56 -> 56, channels-last out
    conv_pad<3, 1, 64, 8, 4, 0, true, true, true><<<dim3(1, 4, 32 * 16), dim3(14, 16)>>>(
        p_c2, p_w3p, b3, p_c3, 60, 58 * 60, 56, 56, 128, 0, 0);
    // 6: ROI coords
    roi_coords<<<(32 * 32 * 100 + 255) / 256, 256>>>(ROI);
    // 7: sampling
    roi_sample<<<dim3(100, 32), dim3(32, 32)>>>();
    // 8-9: FC
    fc_init<<<1024, 256>>>(out, fc_b);
    fc_gemm<<<dim3(4, 16, 8), 256>>>(fc_w, out);
}

// round 12
// speedup vs baseline: 1.1447x; 1.0841x over previous
#include <cuda_runtime.h>
#include <cstdint>

typedef unsigned long long ull;

// ---------------- scratch (device globals; 16B aligned, vector-load strides) ----------------
__device__ __align__(16) float g_x0[32 * 3 * 228 * 232];    // padded input, stride 232
__device__ __align__(16) float g_c1[32 * 32 * 116 * 120];   // conv1 out NCHW, stride 120
__device__ __align__(16) float g_c2[32 * 64 * 58 * 60];     // conv2 out NCHW, stride 60
__device__ __align__(16) float g_c3[32 * 56 * 56 * 128];    // conv3 out channels-LAST
__device__ __align__(16) float g_S [32 * 128 * 3200];       // samples, samp memory order [b][c][n]
__device__ __align__(16) float4 g_pw[32 * 32 * 100];
__device__ __align__(16) int4   g_po[32 * 32 * 100];
__device__ __align__(16) float g_w2p[64 * 32 * 25];
__device__ __align__(16) float g_w3p[128 * 64 * 9];

#define LEAK 0.2f

// ---------------- f32x2 helpers ----------------
__device__ __forceinline__ ull pack2(float lo, float hi) {
    ull r; asm("mov.b64 %0, {%1, %2};" : "=l"(r) : "f"(lo), "f"(hi)); return r;
}
__device__ __forceinline__ void unpack2(ull v, float& lo, float& hi) {
    asm("mov.b64 {%0, %1}, %2;" : "=f"(lo), "=f"(hi) : "l"(v));
}
__device__ __forceinline__ ull ffma2(ull a, ull b, ull c) {
    ull d; asm("fma.rn.f32x2 %0, %1, %2, %3;" : "=l"(d) : "l"(a), "l"(b), "l"(c)); return d;
}

// ---------------- merged pad + halo-zero ----------------
__global__ void padzero(const float* __restrict__ x)
{
    const int idx = blockIdx.x * blockDim.x + threadIdx.x;
    const int NA = 32 * 3 * 228 * 232;
    const int NB = 32 * 32 * 116 * 120;
    const int NC_ = 32 * 64 * 58 * 60;
    if (idx < NA) {
        const int wp = idx % 232;
        const int hp = (idx / 232) % 228;
        const int nc = idx / (232 * 228);
        const int h = hp - 2, w = wp - 2;
        float v = 0.0f;
        if (h >= 0 && h < 224 && w >= 0 && w < 224)
            v = x[(size_t)nc * 224 * 224 + h * 224 + w];
        g_x0[idx] = v;
    } else if (idx < NA + NB) {
        const int j = idx - NA;
        const int w = j % 120;
        const int h = (j / 120) % 116;
        if (h < 2 || h >= 114 || w < 2 || w >= 114) g_c1[j] = 0.0f;
    } else if (idx < NA + NB + NC_) {
        const int j = idx - NA - NB;
        const int w = j % 60;
        const int h = (j / 60) % 58;
        if (h < 1 || h >= 57 || w < 1 || w >= 57) g_c2[j] = 0.0f;
    }
}

// ---------------- weight permute: dst[g][(ci*KK+k)*QC + j] = wt[g*QC+j][ci][k] ----------------
__global__ void permute_wt(const float* __restrict__ wt, float* __restrict__ dst,
                           int CIN, int KK, int QC, int total)
{
    const int t = blockIdx.x * blockDim.x + threadIdx.x;
    if (t >= total) return;
    const int per = CIN * KK * QC;
    const int g = t / per;
    const int r = t % per;
    const int j   = r % QC;
    const int cik = r / QC;
    const int ci = cik / KK;
    const int k  = cik % KK;
    dst[t] = wt[((size_t)(g * QC + j) * CIN + ci) * KK + k];
}

// ---------------- conv + leaky, QC=8, direct LDG.128 input, LDS.128 weight pairs ----------------
template<int KS, int ST, int CIN, int QC, int PX, int OPAD, bool CLAST, bool GUARD, bool PERMW>
__global__ void __launch_bounds__(224, 4)
conv_pad(const float* __restrict__ in, const float* __restrict__ wsrc,
         const float* __restrict__ bias, float* __restrict__ out,
         int Wp, int chanStride, int Hout, int Wout, int Cout,
         int Wop, int outChanStride)
{
    constexpr int JP = QC / 2;
    constexpr int KK = KS * KS;
    constexpr int ISPAN = (PX - 1) * ST + KS;
    constexpr int NL4 = (ISPAN + 3) / 4;

    __shared__ __align__(16) float ws[CIN * KK * QC];

    const int coGroups = Cout / QC;
    const int bb    = blockIdx.z / coGroups;
    const int group = blockIdx.z % coGroups;
    const int cb    = group * QC;
    const int tid   = threadIdx.y * blockDim.x + threadIdx.x;
    const int nthr  = blockDim.x * blockDim.y;

    if (PERMW) {
        const float4* src = (const float4*)(wsrc + (size_t)group * CIN * KK * QC);
        float4* dst = (float4*)ws;
        const int n4 = CIN * KK * QC / 4;
        for (int i = tid; i < n4; i += nthr) dst[i] = src[i];
    } else {
        for (int idx = tid; idx < CIN * KK * QC; idx += nthr) {
            const int j   = idx % QC;
            const int cik = idx / QC;
            const int ci = cik / KK;
            const int k  = cik % KK;
            ws[idx] = wsrc[((size_t)(cb + j) * CIN + ci) * KK + k];
        }
    }
    __syncthreads();

    const int ox0 = threadIdx.x * PX;
    const int oy  = blockIdx.y * blockDim.y + threadIdx.y;
    if (GUARD && oy >= Hout) return;

    ull acc[JP][PX];
#pragma unroll
    for (int jp = 0; jp < JP; jp++) {
        const ull bv = pack2(bias[cb + 2 * jp], bias[cb + 2 * jp + 1]);
#pragma unroll
        for (int px = 0; px < PX; px++) acc[jp][px] = bv;
    }

    const float* ibase = in + (size_t)bb * CIN * chanStride + (size_t)(oy * ST) * Wp + ox0 * ST;

    for (int ci = 0; ci < CIN; ci++) {
        const float* ip = ibase + (size_t)ci * chanStride;
#pragma unroll
        for (int ky = 0; ky < KS; ky++) {
            const float4* rowq = (const float4*)(ip + (size_t)ky * Wp);

            float4 f[NL4];
#pragma unroll
            for (int l = 0; l < NL4; l++) f[l] = rowq[l];

            ull bp[ISPAN];
#pragma unroll
            for (int t = 0; t < ISPAN; t++) {
                const int l = t >> 2, m = t & 3;
                const float v = (m == 0) ? f[l].x : (m == 1) ? f[l].y : (m == 2) ? f[l].z : f[l].w;
                bp[t] = pack2(v, v);
            }

            const float* wrow = ws + (ci * KK + ky * KS) * QC;
#pragma unroll
            for (int kx = 0; kx < KS; kx++) {
                // LDS.128 weight pairs: (w0,w1) and (w2,w3) — wrow + kx*QC is 16B aligned
                const ulonglong2* wq = (const ulonglong2*)(wrow + kx * QC);
                const ulonglong2 wa = wq[0];
                const ulonglong2 wb = wq[1];
#pragma unroll
                for (int px = 0; px < PX; px++) {
                    const ull b2 = bp[px * ST + kx];
                    acc[0][px] = ffma2(wa.x, b2, acc[0][px]);
                    acc[1][px] = ffma2(wa.y, b2, acc[1][px]);
                    acc[2][px] = ffma2(wb.x, b2, acc[2][px]);
                    acc[3][px] = ffma2(wb.y, b2, acc[3][px]);
                }
            }
        }
    }

#pragma unroll
    for (int px = 0; px < PX; px++) {
        const int ox = ox0 + px;
        float v[QC];
#pragma unroll
        for (int jp = 0; jp < JP; jp++) {
            float lo, hi; unpack2(acc[jp][px], lo, hi);
            v[2 * jp]     = lo > 0.0f ? lo : LEAK * lo;
            v[2 * jp + 1] = hi > 0.0f ? hi : LEAK * hi;
        }
        if (CLAST) {
            float* dst = out + (((size_t)(bb * Hout + oy) * Wout + ox) * Cout) + cb;
#pragma unroll
            for (int q = 0; q < QC / 4; q++)
                *(float4*)(dst + q * 4) = make_float4(v[4 * q], v[4 * q + 1], v[4 * q + 2], v[4 * q + 3]);
        } else {
            const size_t base = (size_t)(oy + OPAD) * Wop + ox + OPAD;
#pragma unroll
            for (int j = 0; j < QC; j++)
                out[((size_t)bb * Cout + cb + j) * outChanStride + base] = v[j];
        }
    }
}

// ---------------- ROI coordinate / weight precompute ----------------
__global__ void roi_coords(const float* __restrict__ ROI)
{
    const int t = blockIdx.x * blockDim.x + threadIdx.x;
    if (t >= 32 * 32 * 100) return;
    const int b  = t / 3200;
    const int n  = t % 3200;
    const int rr = n / 100;
    const int g  = n % 100;
    const int gi = g / 10;
    const int gj = g % 10;

    const float* roi = ROI + ((size_t)(b * 32 + rr)) * 7;
    const float cx = roi[0], cy = roi[1];
    const float W1 = roi[2], W2 = roi[3];
    const float H1 = roi[4], H2 = roi[5];
    const float psi = roi[6];

    const float offx = ((float)gj - 4.5f) / 10.0f;
    const float offy = ((float)gi - 4.5f) / 10.0f;

    const float gx = offx * (W1 + W2) - (W1 - W2) * 0.5f;
    const float gy = offy * (H1 + H2) - (H1 - H2) * 0.5f;

    float s, c;
    sincosf(psi, &s, &c);
    const float x = gx * c + gy * s + cx;
    const float y = -gx * s + gy * c + cy;

    const int x0i = (int)floorf(x);
    const int y0i = (int)floorf(y);
    const int x0 = min(max(x0i, 0), 55);
    const int x1 = min(max(x0i + 1, 0), 55);
    const int y0 = min(max(y0i, 0), 55);
    const int y1 = min(max(y0i + 1, 0), 55);

    const float x0f = (float)x0, x1f = (float)x1;
    const float y0f = (float)y0, y1f = (float)y1;

    float step = (x1f - x0f) * (y1f - y0f);
    step = fminf(fmaxf(step, 0.001f), 2.0f);
    const float inv = 1.0f / step;

    float4 w;
    w.x = (x1f - x) * (y1f - y) * inv;
    w.y = (x1f - x) * (y - y0f) * inv;
    w.z = (x - x0f) * (y1f - y) * inv;
    w.w = (x - x0f) * (y - y0f) * inv;

    int4 o;
    o.x = (y0 * 56 + x0) * 128;
    o.y = (y1 * 56 + x0) * 128;
    o.z = (y0 * 56 + x1) * 128;
    o.w = (y1 * 56 + x1) * 128;

    g_pw[t] = w;
    g_po[t] = o;
}

// ---------------- bilinear sample + smem transpose ----------------
__global__ void roi_sample()
{
    __shared__ float sm[32][132];

    const int b  = blockIdx.y;
    const int n0 = blockIdx.x * 32;
    const int cq = threadIdx.x;
    const int y  = threadIdx.y;
    const int n  = n0 + y;

    const float4 w = g_pw[b * 3200 + n];
    const int4   o = g_po[b * 3200 + n];
    const float* feat = g_c3 + (size_t)b * 56 * 56 * 128;

    const float4 A = *(const float4*)(feat + o.x + cq * 4);
    const float4 B = *(const float4*)(feat + o.y + cq * 4);
    const float4 C = *(const float4*)(feat + o.z + cq * 4);
    const float4 D = *(const float4*)(feat + o.w + cq * 4);

    float4 r;
    r.x = A.x * w.x + B.x * w.y + C.x * w.z + D.x * w.w;
    r.y = A.y * w.x + B.y * w.y + C.y * w.z + D.y * w.w;
    r.z = A.z * w.x + B.z * w.y + C.z * w.z + D.z * w.w;
    r.w = A.w * w.x + B.w * w.y + C.w * w.z + D.w * w.w;

    *(float4*)&sm[y][cq * 4] = r;
    __syncthreads();

    const int tid = y * 32 + cq;
    const int c   = tid >> 3;
    const int nq  = tid & 7;
    float4 v;
    v.x = sm[nq * 4 + 0][c];
    v.y = sm[nq * 4 + 1][c];
    v.z = sm[nq * 4 + 2][c];
    v.w = sm[nq * 4 + 3][c];
    *(float4*)(g_S + ((size_t)(b * 128 + c)) * 3200 + n0 + nq * 4) = v;
}

// ---------------- FC ----------------
__global__ void fc_init(float* __restrict__ out, const float* __restrict__ fc_b)
{
    const int t = blockIdx.x * blockDim.x + threadIdx.x;
    if (t < 1024 * 256) out[t] = fc_b[t & 255];
}

// 128x128 tile, BK=32, 256 threads, 8x8 outputs/thread in f32x2, K split 16-way via atomicAdd.
// Per kk: 6 LDS.128 + 32 FFMA2 (84% fma density).
__global__ void __launch_bounds__(256)
fc_gemm(const float* __restrict__ W, float* __restrict__ out)
{
    __shared__ __align__(16) float As2[32][256];   // duplicated A: [k][m*2 + {0,1}]
    __shared__ __align__(16) float Bs [32][128];   // plain B:      [k][n]

    const float* A = g_S;
    const int n0  = blockIdx.x * 128;
    const int m0  = blockIdx.y * 128;
    const int kb0 = blockIdx.z * 800;

    const int tid = threadIdx.x;
    const int ar  = tid >> 1;            // 0..127: row (m for A, n for W)
    const int ac  = (tid & 1) * 16;      // k offset 0 / 16
    const int tr  = tid >> 4;            // 0..15: m-group of 8
    const int tc  = tid & 15;            // 0..15: n-group of 8

    ull acc2[8][4];
#pragma unroll
    for (int i = 0; i < 8; i++)
#pragma unroll
        for (int h = 0; h < 4; h++) acc2[i][h] = 0ull;

    for (int kb = kb0; kb < kb0 + 800; kb += 32) {
        const float* arow = A + (size_t)(m0 + ar) * 12800 + kb + ac;
        const float* brow = W + (size_t)(n0 + ar) * 12800 + kb + ac;
#pragma unroll
        for (int j = 0; j < 4; j++) {
            const float4 av = *(const float4*)(arow + 4 * j);
            *(ull*)&As2[ac + 4 * j + 0][ar * 2] = pack2(av.x, av.x);
            *(ull*)&As2[ac + 4 * j + 1][ar * 2] = pack2(av.y, av.y);
            *(ull*)&As2[ac + 4 * j + 2][ar * 2] = pack2(av.z, av.z);
            *(ull*)&As2[ac + 4 * j + 3][ar * 2] = pack2(av.w, av.w);
            const float4 bv = *(const float4*)(brow + 4 * j);
            Bs[ac + 4 * j + 0][ar] = bv.x;
            Bs[ac + 4 * j + 1][ar] = bv.y;
            Bs[ac + 4 * j + 2][ar] = bv.z;
            Bs[ac + 4 * j + 3][ar] = bv.w;
        }
        __syncthreads();

#pragma unroll
        for (int kk = 0; kk < 32; kk++) {
            const ulonglong2 aA = *(const ulonglong2*)&As2[kk][tr * 16 + 0];   // m0,m1 dup
            const ulonglong2 aB = *(const ulonglong2*)&As2[kk][tr * 16 + 4];   // m2,m3
            const ulonglong2 aC = *(const ulonglong2*)&As2[kk][tr * 16 + 8];   // m4,m5
            const ulonglong2 aD = *(const ulonglong2*)&As2[kk][tr * 16 + 12];  // m6,m7
            const ulonglong2 b01 = *(const ulonglong2*)&Bs[kk][tc * 8];        // n pairs 0,1
            const ulonglong2 b23 = *(const ulonglong2*)&Bs[kk][tc * 8 + 4];    // n pairs 2,3

            acc2[0][0] = ffma2(aA.x, b01.x, acc2[0][0]);
            acc2[0][1] = ffma2(aA.x, b01.y, acc2[0][1]);
            acc2[0][2] = ffma2(aA.x, b23.x, acc2[0][2]);
            acc2[0][3] = ffma2(aA.x, b23.y, acc2[0][3]);
            acc2[1][0] = ffma2(aA.y, b01.x, acc2[1][0]);
            acc2[1][1] = ffma2(aA.y, b01.y, acc2[1][1]);
            acc2[1][2] = ffma2(aA.y, b23.x, acc2[1][2]);
            acc2[1][3] = ffma2(aA.y, b23.y, acc2[1][3]);
            acc2[2][0] = ffma2(aB.x, b01.x, acc2[2][0]);
            acc2[2][1] = ffma2(aB.x, b01.y, acc2[2][1]);
            acc2[2][2] = ffma2(aB.x, b23.x, acc2[2][2]);
            acc2[2][3] = ffma2(aB.x, b23.y, acc2[2][3]);
            acc2[3][0] = ffma2(aB.y, b01.x, acc2[3][0]);
            acc2[3][1] = ffma2(aB.y, b01.y, acc2[3][1]);
            acc2[3][2] = ffma2(aB.y, b23.x, acc2[3][2]);
            acc2[3][3] = ffma2(aB.y, b23.y, acc2[3][3]);
            acc2[4][0] = ffma2(aC.x, b01.x, acc2[4][0]);
            acc2[4][1] = ffma2(aC.x, b01.y, acc2[4][1]);
            acc2[4][2] = ffma2(aC.x, b23.x, acc2[4][2]);
            acc2[4][3] = ffma2(aC.x, b23.y, acc2[4][3]);
            acc2[5][0] = ffma2(aC.y, b01.x, acc2[5][0]);
            acc2[5][1] = ffma2(aC.y, b01.y, acc2[5][1]);
            acc2[5][2] = ffma2(aC.y, b23.x, acc2[5][2]);
            acc2[5][3] = ffma2(aC.y, b23.y, acc2[5][3]);
            acc2[6][0] = ffma2(aD.x, b01.x, acc2[6][0]);
            acc2[6][1] = ffma2(aD.x, b01.y, acc2[6][1]);
            acc2[6][2] = ffma2(aD.x, b23.x, acc2[6][2]);
            acc2[6][3] = ffma2(aD.x, b23.y, acc2[6][3]);
            acc2[7][0] = ffma2(aD.y, b01.x, acc2[7][0]);
            acc2[7][1] = ffma2(aD.y, b01.y, acc2[7][1]);
            acc2[7][2] = ffma2(aD.y, b23.x, acc2[7][2]);
            acc2[7][3] = ffma2(aD.y, b23.y, acc2[7][3]);
        }
        __syncthreads();
    }

#pragma unroll
    for (int i = 0; i < 8; i++) {
        float* dst = out + (size_t)(m0 + tr * 8 + i) * 256 + n0 + tc * 8;
#pragma unroll
        for (int h = 0; h < 4; h++) {
            float f0, f1; unpack2(acc2[i][h], f0, f1);
            atomicAdd(dst + h * 2 + 0, f0);
            atomicAdd(dst + h * 2 + 1, f1);
        }
    }
}

// ---------------- launch ----------------
extern "C" void kernel_launch(void* const* d_in, const int* in_sizes, int n_in,
                              void* d_out, int out_size)
{
    const float* x    = (const float*)d_in[0];
    const float* ROI  = (const float*)d_in[1];
    const float* w1   = (const float*)d_in[2];
    const float* b1   = (const float*)d_in[3];
    const float* w2   = (const float*)d_in[4];
    const float* b2   = (const float*)d_in[5];
    const float* w3   = (const float*)d_in[6];
    const float* b3   = (const float*)d_in[7];
    const float* fc_w = (const float*)d_in[8];
    const float* fc_b = (const float*)d_in[9];
    float* out = (float*)d_out;

    float *p_x0, *p_c1, *p_c2, *p_c3, *p_w2p, *p_w3p;
    cudaGetSymbolAddress((void**)&p_x0, g_x0);
    cudaGetSymbolAddress((void**)&p_c1, g_c1);
    cudaGetSymbolAddress((void**)&p_c2, g_c2);
    cudaGetSymbolAddress((void**)&p_c3, g_c3);
    cudaGetSymbolAddress((void**)&p_w2p, g_w2p);
    cudaGetSymbolAddress((void**)&p_w3p, g_w3p);

    const int NPZ = 32 * 3 * 228 * 232 + 32 * 32 * 116 * 120 + 32 * 64 * 58 * 60;

    // 0: pad input + zero halos (merged)
    padzero<<<(NPZ + 255) / 256, 256>>>(x);
    // 1: permute conv2 weights (QC=8 grouping)
    permute_wt<<<(64 * 32 * 25 + 255) / 256, 256>>>(w2, p_w2p, 32, 25, 8, 64 * 32 * 25);
    // 2: conv1 (inline weight staging): 3 -> 32, 5x5 s2, 224 -> 112
    conv_pad<5, 2, 3, 8, 4, 2, false, false, false><<<dim3(1, 14, 32 * 4), dim3(28, 8)>>>(
        p_x0, w1, b1, p_c1, 232, 228 * 232, 112, 112, 32, 120, 116 * 120);
    // 3: conv2 (PROFILED SLOT): 32 -> 64, 5x5 s2, 112 -> 56
    conv_pad<5, 2, 32, 8, 4, 1, false, true, true><<<dim3(1, 4, 32 * 8), dim3(14, 16)>>>(
        p_c1, p_w2p, b2, p_c2, 120, 116 * 120, 56, 56, 64, 60, 58 * 60);
    // 4: permute conv3 weights (QC=8 grouping)
    permute_wt<<<(128 * 64 * 9 + 255) / 256, 256>>>(w3, p_w3p, 64, 9, 8, 128 * 64 * 9);
    // 5: conv3: 64 -> 128, 3x3 s1, 56 -> 56, channels-last out
    conv_pad<3, 1, 64, 8, 4, 0, true, true, true><<<dim3(1, 4, 32 * 16), dim3(14, 16)>>>(
        p_c2, p_w3p, b3, p_c3, 60, 58 * 60, 56, 56, 128, 0, 0);
    // 6: ROI coords
    roi_coords<<<(32 * 32 * 100 + 255) / 256, 256>>>(ROI);
    // 7: sampling
    roi_sample<<<dim3(100, 32), dim3(32, 32)>>>();
    // 8-9: FC (128x128 tiles, 16-way K split)
    fc_init<<<1024, 256>>>(out, fc_b);
    fc_gemm<<<dim3(2, 8, 16), 256>>>(fc_w, out);
}